// round 13
// baseline (speedup 1.0000x reference)
#include <cuda_runtime.h>
#include <math.h>

#define IMG_W 8192
typedef unsigned long long ull;

// ---------------- scratch ----------------
// acc0 64x128x128 @0, acc1 64x64x64 @1048576, acc2 64x32x32 @1310720,
// acc3 64x16x16 @1376256, acc4 64x8x8 @1392640
__device__ float g_accs[1396736];
__device__ int   g_bounds[4] = {1 << 30, -1, 1 << 30, -1};  // idempotent atomics -> replay-safe
__device__ float g_scale[320];
__device__ float g_shift[320];
__device__ unsigned g_done;
__device__ unsigned g_count = 0;   // grid barrier arrive counter (self-resetting)
__device__ unsigned g_gen   = 0;   // grid barrier generation (monotone -> replay-safe)

#define PACK2(dst, v)  asm("mov.b64 %0, {%1, %1};" : "=l"(dst) : "r"(__float_as_uint(v)))
#define FMA2(acc, a, b) asm("fma.rn.f32x2 %0, %1, %2, %0;" : "+l"(acc) : "l"(a), "l"(b))
#define UNPACK2(lo, hi, v) asm("mov.b64 {%0, %1}, %2;" : "=r"(lo), "=r"(hi) : "l"(v))

template<int L> struct Offs;
template<> struct Offs<0> { static const int v = 0; };
template<> struct Offs<1> { static const int v = 1048576; };
template<> struct Offs<2> { static const int v = 1310720; };
template<> struct Offs<3> { static const int v = 1376256; };
template<> struct Offs<4> { static const int v = 1392640; };

// ---------------- grid-wide barrier (all blocks resident by construction) --------
__device__ __forceinline__ void gsync()
{
    __syncthreads();
    if (threadIdx.x == 0) {
        __threadfence();
        unsigned gen = *(volatile unsigned*)&g_gen;
        if (atomicAdd(&g_count, 1u) == gridDim.x - 1) {
            atomicExch(&g_count, 0u);        // reset BEFORE release
            __threadfence();
            atomicExch(&g_gen, gen + 1u);    // release
        } else {
            while (*(volatile unsigned*)&g_gen == gen) { __nanosleep(64); }
        }
    }
    __syncthreads();
}

// ---------------- fused scan (+prep) -> gsync -> crop/resize/dilate/conv0 --------
// 296 blocks, 2/SM guaranteed resident (tiny smem, low regs) -> gsync is safe.
__global__ void __launch_bounds__(256, 2) scanfront_kernel(
    const float* __restrict__ img,
    const float* __restrict__ w0,
    const float* __restrict__ conv0_b,
    const float* __restrict__ convs_b,
    const float* __restrict__ gamma,
    const float* __restrict__ beta,
    const float* __restrict__ mean,
    const float* __restrict__ var)
{
    __shared__ int smn[256], smx[256];
    __shared__ float s_res[21 * 21];
    __shared__ float s_dil[17 * 17];
    __shared__ float s_w[576];

    const int b = blockIdx.x, tid = threadIdx.x;
    const int gid = b * 256 + tid;

    // ---- phase 0a: prep (zero atomic accumulators, fold BN, reset head counter)
    for (int k = gid; k < 348160; k += 296 * 256) g_accs[1048576 + k] = 0.0f;
    if (gid < 320) {
        int l = gid >> 6, c = gid & 63;
        float sc = gamma[gid] / sqrtf(var[gid] + 1e-5f);
        float bb = (l == 0) ? conv0_b[c] : convs_b[(l - 1) * 64 + c];
        g_scale[gid] = sc;
        g_shift[gid] = (bb - mean[gid]) * sc + beta[gid];
    }
    if (gid == 0) g_done = 0u;

    // ---- phase 0b: variance scans with early exit
    int mn = 1 << 30, mx = -1;
    int lo_idx, hi_idx;
    if (b < 32) {                     // column scan: cols b*256..+255
        lo_idx = 2; hi_idx = 3;
        int c = b * 256 + tid;
        float ref = img[c];
        bool found = false;
        for (int r = 1; r < IMG_W; r++) {
            found |= (img[(size_t)r * IMG_W + c] != ref);
            if (__all_sync(0xffffffffu, found)) break;
        }
        if (found) { mn = c; mx = c; }
    } else {                          // row scan: warp-per-row, grid-stride
        lo_idx = 0; hi_idx = 1;
        const int wid = tid >> 5, lane = tid & 31;
        for (int row = (b - 32) * 8 + wid; row < IMG_W; row += 264 * 8) {
            const float* rowp = img + (size_t)row * IMG_W;
            float v = rowp[lane];
            float ref = __shfl_sync(0xffffffffu, v, 0);
            int flag = __any_sync(0xffffffffu, v != ref) ? 1 : 0;
            for (int base = 32; base < IMG_W && !flag; base += 32)
                flag = __any_sync(0xffffffffu, rowp[base + lane] != ref) ? 1 : 0;
            if (flag) { if (row < mn) mn = row; if (row > mx) mx = row; }
        }
    }

    smn[tid] = mn; smx[tid] = mx;
    __syncthreads();
    for (int s = 128; s > 0; s >>= 1) {
        if (tid < s) { smn[tid] = min(smn[tid], smn[tid + s]); smx[tid] = max(smx[tid], smx[tid + s]); }
        __syncthreads();
    }
    if (tid == 0 && smx[0] >= 0) {
        atomicMin(&g_bounds[lo_idx], smn[0]);
        atomicMax(&g_bounds[hi_idx], smx[0]);
    }

    gsync();   // bounds complete chip-wide (threadfence inside orders atomics)

    // ---- phase 1: front (256 tiles over 296 blocks; blocks >= 256 idle)
    if (b >= 256) return;

    int top = g_bounds[0], bottom = g_bounds[1], left = g_bounds[2], right = g_bounds[3];
    if (bottom < 0) { top = 0; bottom = IMG_W - 1; }
    if (right  < 0) { left = 0; right  = IMG_W - 1; }

    const int ty = b >> 4, tx = b & 15;
    const int oy0 = ty * 8, ox0 = tx * 8;

    for (int i = tid; i < 576; i += 256) s_w[i] = w0[i];

    const int ry0 = 2 * oy0 - 3, rx0 = 2 * ox0 - 3;
    const float szy = (float)(bottom - top + 1);
    const float szx = (float)(right - left + 1);
    for (int i = tid; i < 21 * 21; i += 256) {
        int r = i / 21, c = i - r * 21;
        int gy = ry0 + r, gx = rx0 + c;
        float val = 0.0f;
        if ((unsigned)gy < 256u && (unsigned)gx < 256u) {
            float cy = (float)top  + ((float)gy + 0.5f) * szy * (1.0f / 256.0f) - 0.5f;
            float cx = (float)left + ((float)gx + 0.5f) * szx * (1.0f / 256.0f) - 0.5f;
            float fy0 = floorf(cy), fx0 = floorf(cx);
            float wy = cy - fy0, wx = cx - fx0;
            int y0 = (int)fminf(fmaxf(fy0,        (float)top),  (float)bottom);
            int y1 = (int)fminf(fmaxf(fy0 + 1.0f, (float)top),  (float)bottom);
            int x0 = (int)fminf(fmaxf(fx0,        (float)left), (float)right);
            int x1 = (int)fminf(fmaxf(fx0 + 1.0f, (float)left), (float)right);
            float v00 = img[(size_t)y0 * IMG_W + x0];
            float v01 = img[(size_t)y0 * IMG_W + x1];
            float v10 = img[(size_t)y1 * IMG_W + x0];
            float v11 = img[(size_t)y1 * IMG_W + x1];
            float tr = v00 * (1.0f - wx) + v01 * wx;
            float br = v10 * (1.0f - wx) + v11 * wx;
            val = 255.0f - (tr * (1.0f - wy) + br * wy);
        }
        s_res[i] = val;
    }
    __syncthreads();

    for (int i = tid; i < 17 * 17; i += 256) {
        int r = i / 17, c = i - r * 17;
        int gy = 2 * oy0 - 1 + r, gx = 2 * ox0 - 1 + c;
        float val = 0.0f;
        if ((unsigned)gy < 256u && (unsigned)gx < 256u) {
            float s = 0.0f;
            #pragma unroll
            for (int dy = 0; dy <= 4; dy += 2)
                #pragma unroll
                for (int dx = 0; dx <= 4; dx += 2)
                    s += s_res[(r + dy) * 21 + (c + dx)];
            val = 255.0f - fminf(fmaxf(s, 0.0f), 255.0f);
        }
        s_dil[i] = val;
    }
    __syncthreads();

    const int px = tid >> 2, ocq = tid & 3;
    const int ly = px >> 3, lx = px & 7;
    float v[9];
    #pragma unroll
    for (int ky = 0; ky < 3; ky++)
        #pragma unroll
        for (int kx = 0; kx < 3; kx++)
            v[ky * 3 + kx] = s_dil[(2 * ly + ky) * 17 + (2 * lx + kx)];

    const int oy = oy0 + ly, ox = ox0 + lx;
    #pragma unroll 4
    for (int j = 0; j < 16; j++) {
        int oc = ocq * 16 + j;
        float a = 0.0f;
        #pragma unroll
        for (int k = 0; k < 9; k++) a = fmaf(v[k], s_w[oc * 9 + k], a);
        g_accs[(oc * 128 + oy) * 128 + ox] = a;
    }
}

// ---------------- conv1: 8x8-tile, all-64-oc kernel (champion, unchanged) --------
template<int LAYER, int ICS>
__global__ void __launch_bounds__(256, 3) conv88_kernel(const float* __restrict__ convs_w)
{
    constexpr int HIN  = 256 >> LAYER;
    constexpr int HOUT = HIN >> 1;
    constexpr int TILESX = HOUT >> 3;
    const int tile = blockIdx.x;
    const int ty = tile / TILESX, tx = tile - ty * TILESX;
    const int oy0 = ty * 8, ox0 = tx * 8;
    const int ic0 = blockIdx.y * ICS;

    const float* __restrict__ in  = g_accs + Offs<LAYER - 1>::v;
    float* __restrict__ out       = g_accs + Offs<LAYER>::v;
    const float* __restrict__ w   = convs_w + (LAYER - 1) * 36864;
    const float* __restrict__ scl = g_scale + (LAYER - 1) * 64;
    const float* __restrict__ shf = g_shift + (LAYER - 1) * 64;

    __shared__ __align__(16) float s_w[ICS * 576];
    __shared__ __align__(16) float s_in[ICS * 340];

    const int tid = threadIdx.x;

    constexpr int WPO2 = ICS * 9 / 2;
    constexpr int W2 = 64 * WPO2;
    constexpr int W2IT = (W2 + 255) / 256;
    float2 wq[W2IT];
    #pragma unroll
    for (int i = 0; i < W2IT; i++) {
        int idx = tid + i * 256;
        if (idx < W2) {
            int oc = idx / WPO2, rem2 = idx - oc * WPO2;
            wq[i] = *reinterpret_cast<const float2*>(&w[oc * 576 + ic0 * 9 + rem2 * 2]);
        }
    }

    constexpr int ITOT = ICS * 289;
    constexpr int IIT = (ITOT + 255) / 256;
    float it[IIT];
    const int iy0 = oy0 * 2 - 1, ix0 = ox0 * 2 - 1;
    #pragma unroll
    for (int i = 0; i < IIT; i++) {
        int idx = tid + i * 256;
        if (idx < ITOT) {
            int ch = idx / 289, pos = idx - ch * 289;
            int r = pos / 17, c = pos - r * 17;
            int gy = iy0 + r, gx = ix0 + c;
            bool inb = ((unsigned)gy < (unsigned)HIN) && ((unsigned)gx < (unsigned)HIN);
            it[i] = inb ? __ldg(&in[(ic0 + ch) * HIN * HIN + gy * HIN + gx]) : 0.0f;
        }
    }

    #pragma unroll
    for (int i = 0; i < W2IT; i++) {
        int idx = tid + i * 256;
        if (idx < W2) {
            int oc = idx / WPO2, rem2 = idx - oc * WPO2;
            int f0 = rem2 * 2;
            int ic_a = f0 / 9, k_a = f0 - ic_a * 9;
            s_w[(ic_a * 9 + k_a) * 64 + oc] = wq[i].x;
            int f1 = f0 + 1;
            int ic_b = f1 / 9, k_b = f1 - ic_b * 9;
            s_w[(ic_b * 9 + k_b) * 64 + oc] = wq[i].y;
        }
    }
    #pragma unroll
    for (int i = 0; i < IIT; i++) {
        int idx = tid + i * 256;
        if (idx < ITOT) {
            int ch = idx / 289, pos = idx - ch * 289;
            int r = pos / 17, c = pos - r * 17;
            int ic = ic0 + ch;
            s_in[ch * 340 + r * 20 + c] =
                fmaxf(fmaf(it[i], __ldg(&scl[ic]), __ldg(&shf[ic])), 0.0f);
        }
    }
    __syncthreads();

    const int ocg = tid & 15;
    const int sps = tid >> 4;
    const int my = sps >> 2, mx = sps & 3;

    ull acc[2][4];
    #pragma unroll
    for (int j = 0; j < 2; j++)
        #pragma unroll
        for (int p = 0; p < 4; p++) acc[j][p] = 0ull;

    const float* bp = s_in + (4 * my) * 20 + 4 * mx;

    float4 q[5]; float e[5];
    #pragma unroll
    for (int r = 0; r < 5; r++) {
        q[r] = *reinterpret_cast<const float4*>(bp + r * 20);
        e[r] = bp[r * 20 + 4];
    }

    #pragma unroll
    for (int icc = 0; icc < ICS; icc++) {
        float4 qn[5]; float en[5];
        if (icc + 1 < ICS) {
            const float* bpn = bp + (icc + 1) * 340;
            #pragma unroll
            for (int r = 0; r < 5; r++) {
                qn[r] = *reinterpret_cast<const float4*>(bpn + r * 20);
                en[r] = bpn[r * 20 + 4];
            }
        }
        float win[5][5];
        #pragma unroll
        for (int r = 0; r < 5; r++) {
            win[r][0] = q[r].x; win[r][1] = q[r].y;
            win[r][2] = q[r].z; win[r][3] = q[r].w; win[r][4] = e[r];
        }
        #pragma unroll
        for (int ky = 0; ky < 3; ky++)
            #pragma unroll
            for (int kx = 0; kx < 3; kx++) {
                const int k = ky * 3 + kx;
                ulonglong2 wv = reinterpret_cast<const ulonglong2*>(s_w)[(icc * 9 + k) * 16 + ocg];
                #pragma unroll
                for (int py = 0; py < 2; py++)
                    #pragma unroll
                    for (int px = 0; px < 2; px++) {
                        ull v2;
                        PACK2(v2, win[2 * py + ky][2 * px + kx]);
                        const int p = py * 2 + px;
                        FMA2(acc[0][p], v2, wv.x);
                        FMA2(acc[1][p], v2, wv.y);
                    }
            }
        if (icc + 1 < ICS) {
            #pragma unroll
            for (int r = 0; r < 5; r++) { q[r] = qn[r]; e[r] = en[r]; }
        }
    }

    #pragma unroll
    for (int j = 0; j < 2; j++)
        #pragma unroll
        for (int py = 0; py < 2; py++)
            #pragma unroll
            for (int px = 0; px < 2; px++) {
                unsigned lo, hi;
                UNPACK2(lo, hi, acc[j][py * 2 + px]);
                int oy = oy0 + 2 * my + py, ox = ox0 + 2 * mx + px;
                int oc = ocg * 4 + j * 2;
                atomicAdd(&out[(oc * HOUT + oy) * HOUT + ox], __uint_as_float(lo));
                atomicAdd(&out[((oc + 1) * HOUT + oy) * HOUT + ox], __uint_as_float(hi));
            }
}

// ---------------- conv2-4: convoc with DUPLICATED-INPUT smem (round-12 champ) ----
template<int LAYER, int ICS, bool HEAD>
__global__ void __launch_bounds__(256, 2) convoc_kernel(
    const float* __restrict__ convs_w,
    const float* __restrict__ head_w,
    const float* __restrict__ head_b,
    int* __restrict__ outp)
{
    constexpr int HIN  = 256 >> LAYER;
    constexpr int HOUT = HIN >> 1;
    constexpr int TILESX = HOUT >> 3;
    constexpr int RSTR = 36;            // floats per dup row (17 pairs -> pad 36)
    constexpr int CSTR = 17 * RSTR;     // 612 floats per channel
    const int tile = blockIdx.x;
    const int ty = tile / TILESX, tx = tile - ty * TILESX;
    const int oy0 = ty * 8, ox0 = tx * 8;
    const int ic0 = blockIdx.y * ICS;
    const int ocb = blockIdx.z * 32;

    const float* __restrict__ in  = g_accs + Offs<LAYER - 1>::v;
    float* __restrict__ out       = g_accs + Offs<LAYER>::v;
    const float* __restrict__ w   = convs_w + (LAYER - 1) * 36864;
    const float* __restrict__ scl = g_scale + (LAYER - 1) * 64;
    const float* __restrict__ shf = g_shift + (LAYER - 1) * 64;

    __shared__ __align__(16) float s_w[ICS * 288];   // [(icc*9+k)*32 + ocl]
    __shared__ __align__(16) float s_in[ICS * CSTR]; // dup pairs [ch][r][c][2]

    const int tid = threadIdx.x;

    constexpr int WPO2 = ICS * 9 / 2;
    constexpr int W2 = 32 * WPO2;
    constexpr int W2IT = (W2 + 255) / 256;
    float2 wq[W2IT];
    #pragma unroll
    for (int i = 0; i < W2IT; i++) {
        int idx = tid + i * 256;
        if (idx < W2) {
            int ocl = idx / WPO2, rem2 = idx - ocl * WPO2;
            wq[i] = *reinterpret_cast<const float2*>(&w[(ocb + ocl) * 576 + ic0 * 9 + rem2 * 2]);
        }
    }

    constexpr int ITOT = ICS * 289;
    constexpr int IIT = (ITOT + 255) / 256;
    float it[IIT];
    const int iy0 = oy0 * 2 - 1, ix0 = ox0 * 2 - 1;
    #pragma unroll
    for (int i = 0; i < IIT; i++) {
        int idx = tid + i * 256;
        if (idx < ITOT) {
            int ch = idx / 289, pos = idx - ch * 289;
            int r = pos / 17, c = pos - r * 17;
            int gy = iy0 + r, gx = ix0 + c;
            bool inb = ((unsigned)gy < (unsigned)HIN) && ((unsigned)gx < (unsigned)HIN);
            it[i] = inb ? __ldg(&in[(ic0 + ch) * HIN * HIN + gy * HIN + gx]) : 0.0f;
        }
    }

    #pragma unroll
    for (int i = 0; i < W2IT; i++) {
        int idx = tid + i * 256;
        if (idx < W2) {
            int ocl = idx / WPO2, rem2 = idx - ocl * WPO2;
            int f0 = rem2 * 2;
            int ic_a = f0 / 9, k_a = f0 - ic_a * 9;
            s_w[(ic_a * 9 + k_a) * 32 + ocl] = wq[i].x;
            int f1 = f0 + 1;
            int ic_b = f1 / 9, k_b = f1 - ic_b * 9;
            s_w[(ic_b * 9 + k_b) * 32 + ocl] = wq[i].y;
        }
    }
    #pragma unroll
    for (int i = 0; i < IIT; i++) {
        int idx = tid + i * 256;
        if (idx < ITOT) {
            int ch = idx / 289, pos = idx - ch * 289;
            int r = pos / 17, c = pos - r * 17;
            int ic = ic0 + ch;
            float vv = fmaxf(fmaf(it[i], __ldg(&scl[ic]), __ldg(&shf[ic])), 0.0f);
            ull dv; PACK2(dv, vv);
            *reinterpret_cast<ull*>(&s_in[ch * CSTR + r * RSTR + c * 2]) = dv;
        }
    }
    __syncthreads();

    const int ocg = tid & 7;           // 8 oc-groups of 4
    const int sps = tid >> 3;          // 32 slots: 4x8 grid of 2x1 micros
    const int my = sps >> 3, mx = sps & 7;

    ull acc[2][2];                     // [oc pair][py]
    #pragma unroll
    for (int j = 0; j < 2; j++) { acc[j][0] = 0ull; acc[j][1] = 0ull; }

    const float* bp = s_in + (4 * my) * RSTR + (2 * mx) * 2;

    ulonglong2 a01[5]; ull a2[5];
    #pragma unroll
    for (int r = 0; r < 5; r++) {
        a01[r] = *reinterpret_cast<const ulonglong2*>(bp + r * RSTR);
        a2[r]  = *reinterpret_cast<const ull*>(bp + r * RSTR + 4);
    }

    #pragma unroll
    for (int icc = 0; icc < ICS; icc++) {
        ulonglong2 b01[5]; ull b2[5];
        if (icc + 1 < ICS) {
            const float* bpn = bp + (icc + 1) * CSTR;
            #pragma unroll
            for (int r = 0; r < 5; r++) {
                b01[r] = *reinterpret_cast<const ulonglong2*>(bpn + r * RSTR);
                b2[r]  = *reinterpret_cast<const ull*>(bpn + r * RSTR + 4);
            }
        }
        ull win[5][3];
        #pragma unroll
        for (int r = 0; r < 5; r++) {
            win[r][0] = a01[r].x; win[r][1] = a01[r].y; win[r][2] = a2[r];
        }
        #pragma unroll
        for (int ky = 0; ky < 3; ky++)
            #pragma unroll
            for (int kx = 0; kx < 3; kx++) {
                const int k = ky * 3 + kx;
                ulonglong2 wv = *reinterpret_cast<const ulonglong2*>(
                    s_w + (icc * 9 + k) * 32 + ocg * 4);
                #pragma unroll
                for (int py = 0; py < 2; py++) {
                    ull v2 = win[ky + 2 * py][kx];
                    FMA2(acc[0][py], v2, wv.x);
                    FMA2(acc[1][py], v2, wv.y);
                }
            }
        if (icc + 1 < ICS) {
            #pragma unroll
            for (int r = 0; r < 5; r++) { a01[r] = b01[r]; a2[r] = b2[r]; }
        }
    }

    #pragma unroll
    for (int j = 0; j < 2; j++)
        #pragma unroll
        for (int py = 0; py < 2; py++) {
            unsigned lo, hi;
            UNPACK2(lo, hi, acc[j][py]);
            int oy = oy0 + 2 * my + py, ox = ox0 + mx;
            int oc = ocb + ocg * 4 + j * 2;
            atomicAdd(&out[(oc * HOUT + oy) * HOUT + ox],       __uint_as_float(lo));
            atomicAdd(&out[((oc + 1) * HOUT + oy) * HOUT + ox], __uint_as_float(hi));
        }

    // ---- fused head on the last-finishing conv4 block ----
    if (HEAD) {
        __shared__ unsigned s_last;
        __shared__ float l0[64], l1[64];
        __threadfence();
        __syncthreads();
        if (tid == 0) {
            unsigned total = gridDim.x * gridDim.y * gridDim.z;
            s_last = (atomicAdd(&g_done, 1u) == total - 1) ? 1u : 0u;
        }
        __syncthreads();
        if (s_last) {
            if (tid < 64) {
                __threadfence();
                int c = tid;
                const float* a4 = g_accs + Offs<4>::v;
                float sc = g_scale[256 + c], sh = g_shift[256 + c];
                float s = 0.0f;
                #pragma unroll 8
                for (int p = 0; p < 64; p++) s += fmaxf(fmaf(a4[c * 64 + p], sc, sh), 0.0f);
                float feat = s * (1.0f / 64.0f);
                l0[c] = feat * head_w[c];
                l1[c] = feat * head_w[64 + c];
            }
            __syncthreads();
            if (tid == 0) {
                float A = head_b[0], B = head_b[1];
                for (int i = 0; i < 64; i++) { A += l0[i]; B += l1[i]; }
                outp[0] = (B > A) ? 1 : 0;
            }
        }
    }
}

// ---------------- launch (5 graph nodes) ----------------
extern "C" void kernel_launch(void* const* d_in, const int* in_sizes, int n_in,
                              void* d_out, int out_size)
{
    const float* image   = (const float*)d_in[0];
    const float* conv0_w = (const float*)d_in[1];
    const float* conv0_b = (const float*)d_in[2];
    const float* convs_w = (const float*)d_in[3];
    const float* convs_b = (const float*)d_in[4];
    const float* bn_g    = (const float*)d_in[5];
    const float* bn_b    = (const float*)d_in[6];
    const float* bn_m    = (const float*)d_in[7];
    const float* bn_v    = (const float*)d_in[8];
    const float* head_w  = (const float*)d_in[9];
    const float* head_b  = (const float*)d_in[10];
    int* outp = (int*)d_out;

    scanfront_kernel<<<296, 256>>>(image, conv0_w, conv0_b, convs_b, bn_g, bn_b, bn_m, bn_v);
    conv88_kernel<1, 8><<<dim3(64, 8), 256>>>(convs_w);                                  // 512
    convoc_kernel<2, 8, false><<<dim3(16,  8, 2), 256>>>(convs_w, head_w, head_b, outp); // 256
    convoc_kernel<3, 4, false><<<dim3( 4, 16, 2), 256>>>(convs_w, head_w, head_b, outp); // 128
    convoc_kernel<4, 4, true ><<<dim3( 1, 16, 2), 256>>>(convs_w, head_w, head_b, outp); //  32
}

// round 14
// speedup vs baseline: 1.0033x; 1.0033x over previous
#include <cuda_runtime.h>
#include <math.h>

#define IMG_W 8192
typedef unsigned long long ull;

// ---------------- scratch ----------------
// acc0 64x128x128 @0, acc1 64x64x64 @1048576, acc2 64x32x32 @1310720,
// acc3 64x16x16 @1376256, acc4 64x8x8 @1392640
__device__ float g_accs[1396736];
__device__ int   g_bounds[4] = {1 << 30, -1, 1 << 30, -1};  // idempotent atomics -> replay-safe
__device__ float g_scale[320];
__device__ float g_shift[320];
__device__ unsigned g_done;

#define PACK2(dst, v)  asm("mov.b64 %0, {%1, %1};" : "=l"(dst) : "r"(__float_as_uint(v)))
#define FMA2(acc, a, b) asm("fma.rn.f32x2 %0, %1, %2, %0;" : "+l"(acc) : "l"(a), "l"(b))
#define UNPACK2(lo, hi, v) asm("mov.b64 {%0, %1}, %2;" : "=r"(lo), "=r"(hi) : "l"(v))

template<int L> struct Offs;
template<> struct Offs<0> { static const int v = 0; };
template<> struct Offs<1> { static const int v = 1048576; };
template<> struct Offs<2> { static const int v = 1310720; };
template<> struct Offs<3> { static const int v = 1376256; };
template<> struct Offs<4> { static const int v = 1392640; };

// ---------------- scan (merged with prep work) ------------------------------------
__global__ void scan_kernel(const float* __restrict__ img,
                            const float* __restrict__ conv0_b,
                            const float* __restrict__ convs_b,
                            const float* __restrict__ gamma,
                            const float* __restrict__ beta,
                            const float* __restrict__ mean,
                            const float* __restrict__ var)
{
    __shared__ int smn[256], smx[256];
    const int b = blockIdx.x, tid = threadIdx.x;
    const int gid = b * 256 + tid;

    for (int k = gid; k < 348160; k += 1056 * 256) g_accs[1048576 + k] = 0.0f;
    if (gid < 320) {
        int l = gid >> 6, c = gid & 63;
        float sc = gamma[gid] / sqrtf(var[gid] + 1e-5f);
        float bb = (l == 0) ? conv0_b[c] : convs_b[(l - 1) * 64 + c];
        g_scale[gid] = sc;
        g_shift[gid] = (bb - mean[gid]) * sc + beta[gid];
    }
    if (gid == 0) g_done = 0u;

    int mn = 1 << 30, mx = -1;
    int lo_idx, hi_idx;
    if (b < 32) {                     // column scan, early exit
        lo_idx = 2; hi_idx = 3;
        int c = b * 256 + tid;
        float ref = img[c];
        bool found = false;
        for (int r = 1; r < IMG_W; r++) {
            found |= (img[(size_t)r * IMG_W + c] != ref);
            if (__all_sync(0xffffffffu, found)) break;
        }
        if (found) { mn = c; mx = c; }
    } else {                          // row scan, warp per row
        lo_idx = 0; hi_idx = 1;
        int row = (b - 32) * 8 + (tid >> 5);
        int lane = tid & 31;
        const float* rowp = img + (size_t)row * IMG_W;
        float v = rowp[lane];
        float ref = __shfl_sync(0xffffffffu, v, 0);
        int flag = __any_sync(0xffffffffu, v != ref) ? 1 : 0;
        for (int base = 32; base < IMG_W && !flag; base += 32)
            flag = __any_sync(0xffffffffu, rowp[base + lane] != ref) ? 1 : 0;
        if (lane == 0 && flag) { mn = row; mx = row; }
    }

    smn[tid] = mn; smx[tid] = mx;
    __syncthreads();
    for (int s = 128; s > 0; s >>= 1) {
        if (tid < s) { smn[tid] = min(smn[tid], smn[tid + s]); smx[tid] = max(smx[tid], smx[tid + s]); }
        __syncthreads();
    }
    if (tid == 0 && smx[0] >= 0) {
        atomicMin(&g_bounds[lo_idx], smn[0]);
        atomicMax(&g_bounds[hi_idx], smx[0]);
    }
}

// ---------------- fused crop/resize + dilate + conv0 (8x8 tiles, 256 blocks) -----
__global__ void front_kernel(const float* __restrict__ img, const float* __restrict__ w0)
{
    __shared__ float s_res[21 * 21];
    __shared__ float s_dil[17 * 17];
    __shared__ float s_w[576];
    const int b = blockIdx.x, tid = threadIdx.x;
    const int ty = b >> 4, tx = b & 15;
    const int oy0 = ty * 8, ox0 = tx * 8;

    int top = g_bounds[0], bottom = g_bounds[1], left = g_bounds[2], right = g_bounds[3];
    if (bottom < 0) { top = 0; bottom = IMG_W - 1; }
    if (right  < 0) { left = 0; right  = IMG_W - 1; }

    for (int i = tid; i < 576; i += 256) s_w[i] = w0[i];

    const int ry0 = 2 * oy0 - 3, rx0 = 2 * ox0 - 3;
    const float szy = (float)(bottom - top + 1);
    const float szx = (float)(right - left + 1);
    for (int i = tid; i < 21 * 21; i += 256) {
        int r = i / 21, c = i - r * 21;
        int gy = ry0 + r, gx = rx0 + c;
        float val = 0.0f;
        if ((unsigned)gy < 256u && (unsigned)gx < 256u) {
            float cy = (float)top  + ((float)gy + 0.5f) * szy * (1.0f / 256.0f) - 0.5f;
            float cx = (float)left + ((float)gx + 0.5f) * szx * (1.0f / 256.0f) - 0.5f;
            float fy0 = floorf(cy), fx0 = floorf(cx);
            float wy = cy - fy0, wx = cx - fx0;
            int y0 = (int)fminf(fmaxf(fy0,        (float)top),  (float)bottom);
            int y1 = (int)fminf(fmaxf(fy0 + 1.0f, (float)top),  (float)bottom);
            int x0 = (int)fminf(fmaxf(fx0,        (float)left), (float)right);
            int x1 = (int)fminf(fmaxf(fx0 + 1.0f, (float)left), (float)right);
            float v00 = img[(size_t)y0 * IMG_W + x0];
            float v01 = img[(size_t)y0 * IMG_W + x1];
            float v10 = img[(size_t)y1 * IMG_W + x0];
            float v11 = img[(size_t)y1 * IMG_W + x1];
            float tr = v00 * (1.0f - wx) + v01 * wx;
            float br = v10 * (1.0f - wx) + v11 * wx;
            val = 255.0f - (tr * (1.0f - wy) + br * wy);
        }
        s_res[i] = val;
    }
    __syncthreads();

    for (int i = tid; i < 17 * 17; i += 256) {
        int r = i / 17, c = i - r * 17;
        int gy = 2 * oy0 - 1 + r, gx = 2 * ox0 - 1 + c;
        float val = 0.0f;
        if ((unsigned)gy < 256u && (unsigned)gx < 256u) {
            float s = 0.0f;
            #pragma unroll
            for (int dy = 0; dy <= 4; dy += 2)
                #pragma unroll
                for (int dx = 0; dx <= 4; dx += 2)
                    s += s_res[(r + dy) * 21 + (c + dx)];
            val = 255.0f - fminf(fmaxf(s, 0.0f), 255.0f);
        }
        s_dil[i] = val;
    }
    __syncthreads();

    const int px = tid >> 2, ocq = tid & 3;
    const int ly = px >> 3, lx = px & 7;
    float v[9];
    #pragma unroll
    for (int ky = 0; ky < 3; ky++)
        #pragma unroll
        for (int kx = 0; kx < 3; kx++)
            v[ky * 3 + kx] = s_dil[(2 * ly + ky) * 17 + (2 * lx + kx)];

    const int oy = oy0 + ly, ox = ox0 + lx;
    #pragma unroll 4
    for (int j = 0; j < 16; j++) {
        int oc = ocq * 16 + j;
        float a = 0.0f;
        #pragma unroll
        for (int k = 0; k < 9; k++) a = fmaf(v[k], s_w[oc * 9 + k], a);
        g_accs[(oc * 128 + oy) * 128 + ox] = a;
    }
}

// ---------------- conv1: 8x8-tile, all-64-oc kernel (champion, unchanged) --------
template<int LAYER, int ICS>
__global__ void __launch_bounds__(256, 3) conv88_kernel(const float* __restrict__ convs_w)
{
    constexpr int HIN  = 256 >> LAYER;
    constexpr int HOUT = HIN >> 1;
    constexpr int TILESX = HOUT >> 3;
    const int tile = blockIdx.x;
    const int ty = tile / TILESX, tx = tile - ty * TILESX;
    const int oy0 = ty * 8, ox0 = tx * 8;
    const int ic0 = blockIdx.y * ICS;

    const float* __restrict__ in  = g_accs + Offs<LAYER - 1>::v;
    float* __restrict__ out       = g_accs + Offs<LAYER>::v;
    const float* __restrict__ w   = convs_w + (LAYER - 1) * 36864;
    const float* __restrict__ scl = g_scale + (LAYER - 1) * 64;
    const float* __restrict__ shf = g_shift + (LAYER - 1) * 64;

    __shared__ __align__(16) float s_w[ICS * 576];
    __shared__ __align__(16) float s_in[ICS * 340];

    const int tid = threadIdx.x;

    constexpr int WPO2 = ICS * 9 / 2;
    constexpr int W2 = 64 * WPO2;
    constexpr int W2IT = (W2 + 255) / 256;
    float2 wq[W2IT];
    #pragma unroll
    for (int i = 0; i < W2IT; i++) {
        int idx = tid + i * 256;
        if (idx < W2) {
            int oc = idx / WPO2, rem2 = idx - oc * WPO2;
            wq[i] = *reinterpret_cast<const float2*>(&w[oc * 576 + ic0 * 9 + rem2 * 2]);
        }
    }

    constexpr int ITOT = ICS * 289;
    constexpr int IIT = (ITOT + 255) / 256;
    float it[IIT];
    const int iy0 = oy0 * 2 - 1, ix0 = ox0 * 2 - 1;
    #pragma unroll
    for (int i = 0; i < IIT; i++) {
        int idx = tid + i * 256;
        if (idx < ITOT) {
            int ch = idx / 289, pos = idx - ch * 289;
            int r = pos / 17, c = pos - r * 17;
            int gy = iy0 + r, gx = ix0 + c;
            bool inb = ((unsigned)gy < (unsigned)HIN) && ((unsigned)gx < (unsigned)HIN);
            it[i] = inb ? __ldg(&in[(ic0 + ch) * HIN * HIN + gy * HIN + gx]) : 0.0f;
        }
    }

    #pragma unroll
    for (int i = 0; i < W2IT; i++) {
        int idx = tid + i * 256;
        if (idx < W2) {
            int oc = idx / WPO2, rem2 = idx - oc * WPO2;
            int f0 = rem2 * 2;
            int ic_a = f0 / 9, k_a = f0 - ic_a * 9;
            s_w[(ic_a * 9 + k_a) * 64 + oc] = wq[i].x;
            int f1 = f0 + 1;
            int ic_b = f1 / 9, k_b = f1 - ic_b * 9;
            s_w[(ic_b * 9 + k_b) * 64 + oc] = wq[i].y;
        }
    }
    #pragma unroll
    for (int i = 0; i < IIT; i++) {
        int idx = tid + i * 256;
        if (idx < ITOT) {
            int ch = idx / 289, pos = idx - ch * 289;
            int r = pos / 17, c = pos - r * 17;
            int ic = ic0 + ch;
            s_in[ch * 340 + r * 20 + c] =
                fmaxf(fmaf(it[i], __ldg(&scl[ic]), __ldg(&shf[ic])), 0.0f);
        }
    }
    __syncthreads();

    const int ocg = tid & 15;
    const int sps = tid >> 4;
    const int my = sps >> 2, mx = sps & 3;

    ull acc[2][4];
    #pragma unroll
    for (int j = 0; j < 2; j++)
        #pragma unroll
        for (int p = 0; p < 4; p++) acc[j][p] = 0ull;

    const float* bp = s_in + (4 * my) * 20 + 4 * mx;

    float4 q[5]; float e[5];
    #pragma unroll
    for (int r = 0; r < 5; r++) {
        q[r] = *reinterpret_cast<const float4*>(bp + r * 20);
        e[r] = bp[r * 20 + 4];
    }

    #pragma unroll
    for (int icc = 0; icc < ICS; icc++) {
        float4 qn[5]; float en[5];
        if (icc + 1 < ICS) {
            const float* bpn = bp + (icc + 1) * 340;
            #pragma unroll
            for (int r = 0; r < 5; r++) {
                qn[r] = *reinterpret_cast<const float4*>(bpn + r * 20);
                en[r] = bpn[r * 20 + 4];
            }
        }
        float win[5][5];
        #pragma unroll
        for (int r = 0; r < 5; r++) {
            win[r][0] = q[r].x; win[r][1] = q[r].y;
            win[r][2] = q[r].z; win[r][3] = q[r].w; win[r][4] = e[r];
        }
        #pragma unroll
        for (int ky = 0; ky < 3; ky++)
            #pragma unroll
            for (int kx = 0; kx < 3; kx++) {
                const int k = ky * 3 + kx;
                ulonglong2 wv = reinterpret_cast<const ulonglong2*>(s_w)[(icc * 9 + k) * 16 + ocg];
                #pragma unroll
                for (int py = 0; py < 2; py++)
                    #pragma unroll
                    for (int px = 0; px < 2; px++) {
                        ull v2;
                        PACK2(v2, win[2 * py + ky][2 * px + kx]);
                        const int p = py * 2 + px;
                        FMA2(acc[0][p], v2, wv.x);
                        FMA2(acc[1][p], v2, wv.y);
                    }
            }
        if (icc + 1 < ICS) {
            #pragma unroll
            for (int r = 0; r < 5; r++) { q[r] = qn[r]; e[r] = en[r]; }
        }
    }

    #pragma unroll
    for (int j = 0; j < 2; j++)
        #pragma unroll
        for (int py = 0; py < 2; py++)
            #pragma unroll
            for (int px = 0; px < 2; px++) {
                unsigned lo, hi;
                UNPACK2(lo, hi, acc[j][py * 2 + px]);
                int oy = oy0 + 2 * my + py, ox = ox0 + 2 * mx + px;
                int oc = ocg * 4 + j * 2;
                atomicAdd(&out[(oc * HOUT + oy) * HOUT + ox], __uint_as_float(lo));
                atomicAdd(&out[((oc + 1) * HOUT + oy) * HOUT + ox], __uint_as_float(hi));
            }
}

// ---------------- conv2-4: convoc with DUPLICATED-INPUT smem (round-12 champ) ----
template<int LAYER, int ICS, bool HEAD>
__global__ void __launch_bounds__(256, 2) convoc_kernel(
    const float* __restrict__ convs_w,
    const float* __restrict__ head_w,
    const float* __restrict__ head_b,
    int* __restrict__ outp)
{
    constexpr int HIN  = 256 >> LAYER;
    constexpr int HOUT = HIN >> 1;
    constexpr int TILESX = HOUT >> 3;
    constexpr int RSTR = 36;            // floats per dup row (17 pairs -> pad 36)
    constexpr int CSTR = 17 * RSTR;     // 612 floats per channel
    const int tile = blockIdx.x;
    const int ty = tile / TILESX, tx = tile - ty * TILESX;
    const int oy0 = ty * 8, ox0 = tx * 8;
    const int ic0 = blockIdx.y * ICS;
    const int ocb = blockIdx.z * 32;

    const float* __restrict__ in  = g_accs + Offs<LAYER - 1>::v;
    float* __restrict__ out       = g_accs + Offs<LAYER>::v;
    const float* __restrict__ w   = convs_w + (LAYER - 1) * 36864;
    const float* __restrict__ scl = g_scale + (LAYER - 1) * 64;
    const float* __restrict__ shf = g_shift + (LAYER - 1) * 64;

    __shared__ __align__(16) float s_w[ICS * 288];   // [(icc*9+k)*32 + ocl]
    __shared__ __align__(16) float s_in[ICS * CSTR]; // dup pairs [ch][r][c][2]

    const int tid = threadIdx.x;

    constexpr int WPO2 = ICS * 9 / 2;
    constexpr int W2 = 32 * WPO2;
    constexpr int W2IT = (W2 + 255) / 256;
    float2 wq[W2IT];
    #pragma unroll
    for (int i = 0; i < W2IT; i++) {
        int idx = tid + i * 256;
        if (idx < W2) {
            int ocl = idx / WPO2, rem2 = idx - ocl * WPO2;
            wq[i] = *reinterpret_cast<const float2*>(&w[(ocb + ocl) * 576 + ic0 * 9 + rem2 * 2]);
        }
    }

    constexpr int ITOT = ICS * 289;
    constexpr int IIT = (ITOT + 255) / 256;
    float it[IIT];
    const int iy0 = oy0 * 2 - 1, ix0 = ox0 * 2 - 1;
    #pragma unroll
    for (int i = 0; i < IIT; i++) {
        int idx = tid + i * 256;
        if (idx < ITOT) {
            int ch = idx / 289, pos = idx - ch * 289;
            int r = pos / 17, c = pos - r * 17;
            int gy = iy0 + r, gx = ix0 + c;
            bool inb = ((unsigned)gy < (unsigned)HIN) && ((unsigned)gx < (unsigned)HIN);
            it[i] = inb ? __ldg(&in[(ic0 + ch) * HIN * HIN + gy * HIN + gx]) : 0.0f;
        }
    }

    #pragma unroll
    for (int i = 0; i < W2IT; i++) {
        int idx = tid + i * 256;
        if (idx < W2) {
            int ocl = idx / WPO2, rem2 = idx - ocl * WPO2;
            int f0 = rem2 * 2;
            int ic_a = f0 / 9, k_a = f0 - ic_a * 9;
            s_w[(ic_a * 9 + k_a) * 32 + ocl] = wq[i].x;
            int f1 = f0 + 1;
            int ic_b = f1 / 9, k_b = f1 - ic_b * 9;
            s_w[(ic_b * 9 + k_b) * 32 + ocl] = wq[i].y;
        }
    }
    #pragma unroll
    for (int i = 0; i < IIT; i++) {
        int idx = tid + i * 256;
        if (idx < ITOT) {
            int ch = idx / 289, pos = idx - ch * 289;
            int r = pos / 17, c = pos - r * 17;
            int ic = ic0 + ch;
            float vv = fmaxf(fmaf(it[i], __ldg(&scl[ic]), __ldg(&shf[ic])), 0.0f);
            ull dv; PACK2(dv, vv);
            *reinterpret_cast<ull*>(&s_in[ch * CSTR + r * RSTR + c * 2]) = dv;
        }
    }
    __syncthreads();

    const int ocg = tid & 7;           // 8 oc-groups of 4
    const int sps = tid >> 3;          // 32 slots: 4x8 grid of 2x1 micros
    const int my = sps >> 3, mx = sps & 7;

    ull acc[2][2];                     // [oc pair][py]
    #pragma unroll
    for (int j = 0; j < 2; j++) { acc[j][0] = 0ull; acc[j][1] = 0ull; }

    const float* bp = s_in + (4 * my) * RSTR + (2 * mx) * 2;

    ulonglong2 a01[5]; ull a2[5];
    #pragma unroll
    for (int r = 0; r < 5; r++) {
        a01[r] = *reinterpret_cast<const ulonglong2*>(bp + r * RSTR);
        a2[r]  = *reinterpret_cast<const ull*>(bp + r * RSTR + 4);
    }

    #pragma unroll
    for (int icc = 0; icc < ICS; icc++) {
        ulonglong2 b01[5]; ull b2[5];
        if (icc + 1 < ICS) {
            const float* bpn = bp + (icc + 1) * CSTR;
            #pragma unroll
            for (int r = 0; r < 5; r++) {
                b01[r] = *reinterpret_cast<const ulonglong2*>(bpn + r * RSTR);
                b2[r]  = *reinterpret_cast<const ull*>(bpn + r * RSTR + 4);
            }
        }
        ull win[5][3];
        #pragma unroll
        for (int r = 0; r < 5; r++) {
            win[r][0] = a01[r].x; win[r][1] = a01[r].y; win[r][2] = a2[r];
        }
        #pragma unroll
        for (int ky = 0; ky < 3; ky++)
            #pragma unroll
            for (int kx = 0; kx < 3; kx++) {
                const int k = ky * 3 + kx;
                ulonglong2 wv = *reinterpret_cast<const ulonglong2*>(
                    s_w + (icc * 9 + k) * 32 + ocg * 4);
                #pragma unroll
                for (int py = 0; py < 2; py++) {
                    ull v2 = win[ky + 2 * py][kx];
                    FMA2(acc[0][py], v2, wv.x);
                    FMA2(acc[1][py], v2, wv.y);
                }
            }
        if (icc + 1 < ICS) {
            #pragma unroll
            for (int r = 0; r < 5; r++) { a01[r] = b01[r]; a2[r] = b2[r]; }
        }
    }

    #pragma unroll
    for (int j = 0; j < 2; j++)
        #pragma unroll
        for (int py = 0; py < 2; py++) {
            unsigned lo, hi;
            UNPACK2(lo, hi, acc[j][py]);
            int oy = oy0 + 2 * my + py, ox = ox0 + mx;
            int oc = ocb + ocg * 4 + j * 2;
            atomicAdd(&out[(oc * HOUT + oy) * HOUT + ox],       __uint_as_float(lo));
            atomicAdd(&out[((oc + 1) * HOUT + oy) * HOUT + ox], __uint_as_float(hi));
        }

    // ---- fused head on the last-finishing conv4 block ----
    if (HEAD) {
        __shared__ unsigned s_last;
        __shared__ float l0[64], l1[64];
        __threadfence();
        __syncthreads();
        if (tid == 0) {
            unsigned total = gridDim.x * gridDim.y * gridDim.z;
            s_last = (atomicAdd(&g_done, 1u) == total - 1) ? 1u : 0u;
        }
        __syncthreads();
        if (s_last) {
            if (tid < 64) {
                __threadfence();
                int c = tid;
                const float* a4 = g_accs + Offs<4>::v;
                float sc = g_scale[256 + c], sh = g_shift[256 + c];
                float s = 0.0f;
                #pragma unroll 8
                for (int p = 0; p < 64; p++) s += fmaxf(fmaf(a4[c * 64 + p], sc, sh), 0.0f);
                float feat = s * (1.0f / 64.0f);
                l0[c] = feat * head_w[c];
                l1[c] = feat * head_w[64 + c];
            }
            __syncthreads();
            if (tid == 0) {
                float A = head_b[0], B = head_b[1];
                for (int i = 0; i < 64; i++) { A += l0[i]; B += l1[i]; }
                outp[0] = (B > A) ? 1 : 0;
            }
        }
    }
}

// ---------------- launch (6 graph nodes) ----------------
extern "C" void kernel_launch(void* const* d_in, const int* in_sizes, int n_in,
                              void* d_out, int out_size)
{
    const float* image   = (const float*)d_in[0];
    const float* conv0_w = (const float*)d_in[1];
    const float* conv0_b = (const float*)d_in[2];
    const float* convs_w = (const float*)d_in[3];
    const float* convs_b = (const float*)d_in[4];
    const float* bn_g    = (const float*)d_in[5];
    const float* bn_b    = (const float*)d_in[6];
    const float* bn_m    = (const float*)d_in[7];
    const float* bn_v    = (const float*)d_in[8];
    const float* head_w  = (const float*)d_in[9];
    const float* head_b  = (const float*)d_in[10];
    int* outp = (int*)d_out;

    scan_kernel<<<1056, 256>>>(image, conv0_b, convs_b, bn_g, bn_b, bn_m, bn_v);
    front_kernel<<<256, 256>>>(image, conv0_w);
    conv88_kernel<1, 8><<<dim3(64, 8), 256>>>(convs_w);                                  // 512
    convoc_kernel<2, 8, false><<<dim3(16,  8, 2), 256>>>(convs_w, head_w, head_b, outp); // 256
    convoc_kernel<3, 8, false><<<dim3( 4,  8, 2), 256>>>(convs_w, head_w, head_b, outp); //  64
    convoc_kernel<4, 4, true ><<<dim3( 1, 16, 2), 256>>>(convs_w, head_w, head_b, outp); //  32
}

// round 15
// speedup vs baseline: 1.0391x; 1.0356x over previous
#include <cuda_runtime.h>
#include <math.h>

#define IMG_W 8192
typedef unsigned long long ull;

// ---------------- scratch ----------------
// acc0 64x128x128 @0, acc1 64x64x64 @1048576, acc2 64x32x32 @1310720,
// acc3 64x16x16 @1376256, acc4 64x8x8 @1392640
__device__ float g_accs[1396736];
__device__ int   g_bounds[4] = {1 << 30, -1, 1 << 30, -1};  // idempotent atomics -> replay-safe
__device__ float g_scale[320];
__device__ float g_shift[320];
__device__ unsigned g_done;

#define PACK2(dst, v)  asm("mov.b64 %0, {%1, %1};" : "=l"(dst) : "r"(__float_as_uint(v)))
#define FMA2(acc, a, b) asm("fma.rn.f32x2 %0, %1, %2, %0;" : "+l"(acc) : "l"(a), "l"(b))
#define UNPACK2(lo, hi, v) asm("mov.b64 {%0, %1}, %2;" : "=r"(lo), "=r"(hi) : "l"(v))

template<int L> struct Offs;
template<> struct Offs<0> { static const int v = 0; };
template<> struct Offs<1> { static const int v = 1048576; };
template<> struct Offs<2> { static const int v = 1310720; };
template<> struct Offs<3> { static const int v = 1376256; };
template<> struct Offs<4> { static const int v = 1392640; };

// ---------------- scan (merged with prep), 544 blocks -----------------------------
// blocks [0,32): column scan (1 col/thread). blocks [32,544): row scan, 2 rows/warp
// with PARALLEL first-chunk probes (independent LDGs overlap); serial fallback only
// for rows whose first 32 elements are constant (correctness path, ~never taken).
__global__ void scan_kernel(const float* __restrict__ img,
                            const float* __restrict__ conv0_b,
                            const float* __restrict__ convs_b,
                            const float* __restrict__ gamma,
                            const float* __restrict__ beta,
                            const float* __restrict__ mean,
                            const float* __restrict__ var)
{
    __shared__ int smn[256], smx[256];
    const int b = blockIdx.x, tid = threadIdx.x;
    const int gid = b * 256 + tid;

    for (int k = gid; k < 348160; k += 544 * 256) g_accs[1048576 + k] = 0.0f;
    if (gid < 320) {
        int l = gid >> 6, c = gid & 63;
        float sc = gamma[gid] / sqrtf(var[gid] + 1e-5f);
        float bb = (l == 0) ? conv0_b[c] : convs_b[(l - 1) * 64 + c];
        g_scale[gid] = sc;
        g_shift[gid] = (bb - mean[gid]) * sc + beta[gid];
    }
    if (gid == 0) g_done = 0u;

    int mn = 1 << 30, mx = -1;
    int lo_idx, hi_idx;
    if (b < 32) {                     // column scan, early exit
        lo_idx = 2; hi_idx = 3;
        int c = b * 256 + tid;
        float ref = img[c];
        bool found = false;
        for (int r = 1; r < IMG_W; r++) {
            found |= (img[(size_t)r * IMG_W + c] != ref);
            if (__all_sync(0xffffffffu, found)) break;
        }
        if (found) { mn = c; mx = c; }
    } else {                          // row scan: 2 rows per warp, parallel probes
        lo_idx = 0; hi_idx = 1;
        const int wid = tid >> 5, lane = tid & 31;
        const int row0 = ((b - 32) * 8 + wid) * 2;   // rows row0, row0+1
        const float* rp0 = img + (size_t)row0 * IMG_W;
        const float* rp1 = rp0 + IMG_W;
        float v0 = rp0[lane];                         // both probes issued before use
        float v1 = rp1[lane];
        float ref0 = __shfl_sync(0xffffffffu, v0, 0);
        float ref1 = __shfl_sync(0xffffffffu, v1, 0);
        int f0 = __any_sync(0xffffffffu, v0 != ref0) ? 1 : 0;
        int f1 = __any_sync(0xffffffffu, v1 != ref1) ? 1 : 0;
        for (int base = 32; base < IMG_W && !f0; base += 32)    // fallback (rare)
            f0 = __any_sync(0xffffffffu, rp0[base + lane] != ref0) ? 1 : 0;
        for (int base = 32; base < IMG_W && !f1; base += 32)
            f1 = __any_sync(0xffffffffu, rp1[base + lane] != ref1) ? 1 : 0;
        if (lane == 0) {
            if (f0) { mn = row0; mx = row0; }
            if (f1) { if (row0 + 1 < mn) mn = row0 + 1; if (row0 + 1 > mx) mx = row0 + 1; }
        }
    }

    smn[tid] = mn; smx[tid] = mx;
    __syncthreads();
    for (int s = 128; s > 0; s >>= 1) {
        if (tid < s) { smn[tid] = min(smn[tid], smn[tid + s]); smx[tid] = max(smx[tid], smx[tid + s]); }
        __syncthreads();
    }
    if (tid == 0 && smx[0] >= 0) {
        atomicMin(&g_bounds[lo_idx], smn[0]);
        atomicMax(&g_bounds[hi_idx], smx[0]);
    }
}

// ---------------- fused crop/resize + dilate + conv0 (8x8 tiles, 256 blocks) -----
__global__ void front_kernel(const float* __restrict__ img, const float* __restrict__ w0)
{
    __shared__ float s_res[21 * 21];
    __shared__ float s_dil[17 * 17];
    __shared__ float s_w[576];
    const int b = blockIdx.x, tid = threadIdx.x;
    const int ty = b >> 4, tx = b & 15;
    const int oy0 = ty * 8, ox0 = tx * 8;

    int top = g_bounds[0], bottom = g_bounds[1], left = g_bounds[2], right = g_bounds[3];
    if (bottom < 0) { top = 0; bottom = IMG_W - 1; }
    if (right  < 0) { left = 0; right  = IMG_W - 1; }

    for (int i = tid; i < 576; i += 256) s_w[i] = w0[i];

    const int ry0 = 2 * oy0 - 3, rx0 = 2 * ox0 - 3;
    const float szy = (float)(bottom - top + 1);
    const float szx = (float)(right - left + 1);
    for (int i = tid; i < 21 * 21; i += 256) {
        int r = i / 21, c = i - r * 21;
        int gy = ry0 + r, gx = rx0 + c;
        float val = 0.0f;
        if ((unsigned)gy < 256u && (unsigned)gx < 256u) {
            float cy = (float)top  + ((float)gy + 0.5f) * szy * (1.0f / 256.0f) - 0.5f;
            float cx = (float)left + ((float)gx + 0.5f) * szx * (1.0f / 256.0f) - 0.5f;
            float fy0 = floorf(cy), fx0 = floorf(cx);
            float wy = cy - fy0, wx = cx - fx0;
            int y0 = (int)fminf(fmaxf(fy0,        (float)top),  (float)bottom);
            int y1 = (int)fminf(fmaxf(fy0 + 1.0f, (float)top),  (float)bottom);
            int x0 = (int)fminf(fmaxf(fx0,        (float)left), (float)right);
            int x1 = (int)fminf(fmaxf(fx0 + 1.0f, (float)left), (float)right);
            float v00 = img[(size_t)y0 * IMG_W + x0];
            float v01 = img[(size_t)y0 * IMG_W + x1];
            float v10 = img[(size_t)y1 * IMG_W + x0];
            float v11 = img[(size_t)y1 * IMG_W + x1];
            float tr = v00 * (1.0f - wx) + v01 * wx;
            float br = v10 * (1.0f - wx) + v11 * wx;
            val = 255.0f - (tr * (1.0f - wy) + br * wy);
        }
        s_res[i] = val;
    }
    __syncthreads();

    for (int i = tid; i < 17 * 17; i += 256) {
        int r = i / 17, c = i - r * 17;
        int gy = 2 * oy0 - 1 + r, gx = 2 * ox0 - 1 + c;
        float val = 0.0f;
        if ((unsigned)gy < 256u && (unsigned)gx < 256u) {
            float s = 0.0f;
            #pragma unroll
            for (int dy = 0; dy <= 4; dy += 2)
                #pragma unroll
                for (int dx = 0; dx <= 4; dx += 2)
                    s += s_res[(r + dy) * 21 + (c + dx)];
            val = 255.0f - fminf(fmaxf(s, 0.0f), 255.0f);
        }
        s_dil[i] = val;
    }
    __syncthreads();

    const int px = tid >> 2, ocq = tid & 3;
    const int ly = px >> 3, lx = px & 7;
    float v[9];
    #pragma unroll
    for (int ky = 0; ky < 3; ky++)
        #pragma unroll
        for (int kx = 0; kx < 3; kx++)
            v[ky * 3 + kx] = s_dil[(2 * ly + ky) * 17 + (2 * lx + kx)];

    const int oy = oy0 + ly, ox = ox0 + lx;
    #pragma unroll 4
    for (int j = 0; j < 16; j++) {
        int oc = ocq * 16 + j;
        float a = 0.0f;
        #pragma unroll
        for (int k = 0; k < 9; k++) a = fmaf(v[k], s_w[oc * 9 + k], a);
        g_accs[(oc * 128 + oy) * 128 + ox] = a;
    }
}

// ---------------- conv1: 8x8-tile, all-64-oc kernel (champion, unchanged) --------
template<int LAYER, int ICS>
__global__ void __launch_bounds__(256, 3) conv88_kernel(const float* __restrict__ convs_w)
{
    constexpr int HIN  = 256 >> LAYER;
    constexpr int HOUT = HIN >> 1;
    constexpr int TILESX = HOUT >> 3;
    const int tile = blockIdx.x;
    const int ty = tile / TILESX, tx = tile - ty * TILESX;
    const int oy0 = ty * 8, ox0 = tx * 8;
    const int ic0 = blockIdx.y * ICS;

    const float* __restrict__ in  = g_accs + Offs<LAYER - 1>::v;
    float* __restrict__ out       = g_accs + Offs<LAYER>::v;
    const float* __restrict__ w   = convs_w + (LAYER - 1) * 36864;
    const float* __restrict__ scl = g_scale + (LAYER - 1) * 64;
    const float* __restrict__ shf = g_shift + (LAYER - 1) * 64;

    __shared__ __align__(16) float s_w[ICS * 576];
    __shared__ __align__(16) float s_in[ICS * 340];

    const int tid = threadIdx.x;

    constexpr int WPO2 = ICS * 9 / 2;
    constexpr int W2 = 64 * WPO2;
    constexpr int W2IT = (W2 + 255) / 256;
    float2 wq[W2IT];
    #pragma unroll
    for (int i = 0; i < W2IT; i++) {
        int idx = tid + i * 256;
        if (idx < W2) {
            int oc = idx / WPO2, rem2 = idx - oc * WPO2;
            wq[i] = *reinterpret_cast<const float2*>(&w[oc * 576 + ic0 * 9 + rem2 * 2]);
        }
    }

    constexpr int ITOT = ICS * 289;
    constexpr int IIT = (ITOT + 255) / 256;
    float it[IIT];
    const int iy0 = oy0 * 2 - 1, ix0 = ox0 * 2 - 1;
    #pragma unroll
    for (int i = 0; i < IIT; i++) {
        int idx = tid + i * 256;
        if (idx < ITOT) {
            int ch = idx / 289, pos = idx - ch * 289;
            int r = pos / 17, c = pos - r * 17;
            int gy = iy0 + r, gx = ix0 + c;
            bool inb = ((unsigned)gy < (unsigned)HIN) && ((unsigned)gx < (unsigned)HIN);
            it[i] = inb ? __ldg(&in[(ic0 + ch) * HIN * HIN + gy * HIN + gx]) : 0.0f;
        }
    }

    #pragma unroll
    for (int i = 0; i < W2IT; i++) {
        int idx = tid + i * 256;
        if (idx < W2) {
            int oc = idx / WPO2, rem2 = idx - oc * WPO2;
            int f0 = rem2 * 2;
            int ic_a = f0 / 9, k_a = f0 - ic_a * 9;
            s_w[(ic_a * 9 + k_a) * 64 + oc] = wq[i].x;
            int f1 = f0 + 1;
            int ic_b = f1 / 9, k_b = f1 - ic_b * 9;
            s_w[(ic_b * 9 + k_b) * 64 + oc] = wq[i].y;
        }
    }
    #pragma unroll
    for (int i = 0; i < IIT; i++) {
        int idx = tid + i * 256;
        if (idx < ITOT) {
            int ch = idx / 289, pos = idx - ch * 289;
            int r = pos / 17, c = pos - r * 17;
            int ic = ic0 + ch;
            s_in[ch * 340 + r * 20 + c] =
                fmaxf(fmaf(it[i], __ldg(&scl[ic]), __ldg(&shf[ic])), 0.0f);
        }
    }
    __syncthreads();

    const int ocg = tid & 15;
    const int sps = tid >> 4;
    const int my = sps >> 2, mx = sps & 3;

    ull acc[2][4];
    #pragma unroll
    for (int j = 0; j < 2; j++)
        #pragma unroll
        for (int p = 0; p < 4; p++) acc[j][p] = 0ull;

    const float* bp = s_in + (4 * my) * 20 + 4 * mx;

    float4 q[5]; float e[5];
    #pragma unroll
    for (int r = 0; r < 5; r++) {
        q[r] = *reinterpret_cast<const float4*>(bp + r * 20);
        e[r] = bp[r * 20 + 4];
    }

    #pragma unroll
    for (int icc = 0; icc < ICS; icc++) {
        float4 qn[5]; float en[5];
        if (icc + 1 < ICS) {
            const float* bpn = bp + (icc + 1) * 340;
            #pragma unroll
            for (int r = 0; r < 5; r++) {
                qn[r] = *reinterpret_cast<const float4*>(bpn + r * 20);
                en[r] = bpn[r * 20 + 4];
            }
        }
        float win[5][5];
        #pragma unroll
        for (int r = 0; r < 5; r++) {
            win[r][0] = q[r].x; win[r][1] = q[r].y;
            win[r][2] = q[r].z; win[r][3] = q[r].w; win[r][4] = e[r];
        }
        #pragma unroll
        for (int ky = 0; ky < 3; ky++)
            #pragma unroll
            for (int kx = 0; kx < 3; kx++) {
                const int k = ky * 3 + kx;
                ulonglong2 wv = reinterpret_cast<const ulonglong2*>(s_w)[(icc * 9 + k) * 16 + ocg];
                #pragma unroll
                for (int py = 0; py < 2; py++)
                    #pragma unroll
                    for (int px = 0; px < 2; px++) {
                        ull v2;
                        PACK2(v2, win[2 * py + ky][2 * px + kx]);
                        const int p = py * 2 + px;
                        FMA2(acc[0][p], v2, wv.x);
                        FMA2(acc[1][p], v2, wv.y);
                    }
            }
        if (icc + 1 < ICS) {
            #pragma unroll
            for (int r = 0; r < 5; r++) { q[r] = qn[r]; e[r] = en[r]; }
        }
    }

    #pragma unroll
    for (int j = 0; j < 2; j++)
        #pragma unroll
        for (int py = 0; py < 2; py++)
            #pragma unroll
            for (int px = 0; px < 2; px++) {
                unsigned lo, hi;
                UNPACK2(lo, hi, acc[j][py * 2 + px]);
                int oy = oy0 + 2 * my + py, ox = ox0 + 2 * mx + px;
                int oc = ocg * 4 + j * 2;
                atomicAdd(&out[(oc * HOUT + oy) * HOUT + ox], __uint_as_float(lo));
                atomicAdd(&out[((oc + 1) * HOUT + oy) * HOUT + ox], __uint_as_float(hi));
            }
}

// ---------------- conv2-4: convoc with DUPLICATED-INPUT smem (round-12 champ) ----
template<int LAYER, int ICS, bool HEAD>
__global__ void __launch_bounds__(256, 2) convoc_kernel(
    const float* __restrict__ convs_w,
    const float* __restrict__ head_w,
    const float* __restrict__ head_b,
    int* __restrict__ outp)
{
    constexpr int HIN  = 256 >> LAYER;
    constexpr int HOUT = HIN >> 1;
    constexpr int TILESX = HOUT >> 3;
    constexpr int RSTR = 36;            // floats per dup row (17 pairs -> pad 36)
    constexpr int CSTR = 17 * RSTR;     // 612 floats per channel
    const int tile = blockIdx.x;
    const int ty = tile / TILESX, tx = tile - ty * TILESX;
    const int oy0 = ty * 8, ox0 = tx * 8;
    const int ic0 = blockIdx.y * ICS;
    const int ocb = blockIdx.z * 32;

    const float* __restrict__ in  = g_accs + Offs<LAYER - 1>::v;
    float* __restrict__ out       = g_accs + Offs<LAYER>::v;
    const float* __restrict__ w   = convs_w + (LAYER - 1) * 36864;
    const float* __restrict__ scl = g_scale + (LAYER - 1) * 64;
    const float* __restrict__ shf = g_shift + (LAYER - 1) * 64;

    __shared__ __align__(16) float s_w[ICS * 288];   // [(icc*9+k)*32 + ocl]
    __shared__ __align__(16) float s_in[ICS * CSTR]; // dup pairs [ch][r][c][2]

    const int tid = threadIdx.x;

    constexpr int WPO2 = ICS * 9 / 2;
    constexpr int W2 = 32 * WPO2;
    constexpr int W2IT = (W2 + 255) / 256;
    float2 wq[W2IT];
    #pragma unroll
    for (int i = 0; i < W2IT; i++) {
        int idx = tid + i * 256;
        if (idx < W2) {
            int ocl = idx / WPO2, rem2 = idx - ocl * WPO2;
            wq[i] = *reinterpret_cast<const float2*>(&w[(ocb + ocl) * 576 + ic0 * 9 + rem2 * 2]);
        }
    }

    constexpr int ITOT = ICS * 289;
    constexpr int IIT = (ITOT + 255) / 256;
    float it[IIT];
    const int iy0 = oy0 * 2 - 1, ix0 = ox0 * 2 - 1;
    #pragma unroll
    for (int i = 0; i < IIT; i++) {
        int idx = tid + i * 256;
        if (idx < ITOT) {
            int ch = idx / 289, pos = idx - ch * 289;
            int r = pos / 17, c = pos - r * 17;
            int gy = iy0 + r, gx = ix0 + c;
            bool inb = ((unsigned)gy < (unsigned)HIN) && ((unsigned)gx < (unsigned)HIN);
            it[i] = inb ? __ldg(&in[(ic0 + ch) * HIN * HIN + gy * HIN + gx]) : 0.0f;
        }
    }

    #pragma unroll
    for (int i = 0; i < W2IT; i++) {
        int idx = tid + i * 256;
        if (idx < W2) {
            int ocl = idx / WPO2, rem2 = idx - ocl * WPO2;
            int f0 = rem2 * 2;
            int ic_a = f0 / 9, k_a = f0 - ic_a * 9;
            s_w[(ic_a * 9 + k_a) * 32 + ocl] = wq[i].x;
            int f1 = f0 + 1;
            int ic_b = f1 / 9, k_b = f1 - ic_b * 9;
            s_w[(ic_b * 9 + k_b) * 32 + ocl] = wq[i].y;
        }
    }
    #pragma unroll
    for (int i = 0; i < IIT; i++) {
        int idx = tid + i * 256;
        if (idx < ITOT) {
            int ch = idx / 289, pos = idx - ch * 289;
            int r = pos / 17, c = pos - r * 17;
            int ic = ic0 + ch;
            float vv = fmaxf(fmaf(it[i], __ldg(&scl[ic]), __ldg(&shf[ic])), 0.0f);
            ull dv; PACK2(dv, vv);
            *reinterpret_cast<ull*>(&s_in[ch * CSTR + r * RSTR + c * 2]) = dv;
        }
    }
    __syncthreads();

    const int ocg = tid & 7;           // 8 oc-groups of 4
    const int sps = tid >> 3;          // 32 slots: 4x8 grid of 2x1 micros
    const int my = sps >> 3, mx = sps & 7;

    ull acc[2][2];                     // [oc pair][py]
    #pragma unroll
    for (int j = 0; j < 2; j++) { acc[j][0] = 0ull; acc[j][1] = 0ull; }

    const float* bp = s_in + (4 * my) * RSTR + (2 * mx) * 2;

    ulonglong2 a01[5]; ull a2[5];
    #pragma unroll
    for (int r = 0; r < 5; r++) {
        a01[r] = *reinterpret_cast<const ulonglong2*>(bp + r * RSTR);
        a2[r]  = *reinterpret_cast<const ull*>(bp + r * RSTR + 4);
    }

    #pragma unroll
    for (int icc = 0; icc < ICS; icc++) {
        ulonglong2 b01[5]; ull b2[5];
        if (icc + 1 < ICS) {
            const float* bpn = bp + (icc + 1) * CSTR;
            #pragma unroll
            for (int r = 0; r < 5; r++) {
                b01[r] = *reinterpret_cast<const ulonglong2*>(bpn + r * RSTR);
                b2[r]  = *reinterpret_cast<const ull*>(bpn + r * RSTR + 4);
            }
        }
        ull win[5][3];
        #pragma unroll
        for (int r = 0; r < 5; r++) {
            win[r][0] = a01[r].x; win[r][1] = a01[r].y; win[r][2] = a2[r];
        }
        #pragma unroll
        for (int ky = 0; ky < 3; ky++)
            #pragma unroll
            for (int kx = 0; kx < 3; kx++) {
                const int k = ky * 3 + kx;
                ulonglong2 wv = *reinterpret_cast<const ulonglong2*>(
                    s_w + (icc * 9 + k) * 32 + ocg * 4);
                #pragma unroll
                for (int py = 0; py < 2; py++) {
                    ull v2 = win[ky + 2 * py][kx];
                    FMA2(acc[0][py], v2, wv.x);
                    FMA2(acc[1][py], v2, wv.y);
                }
            }
        if (icc + 1 < ICS) {
            #pragma unroll
            for (int r = 0; r < 5; r++) { a01[r] = b01[r]; a2[r] = b2[r]; }
        }
    }

    #pragma unroll
    for (int j = 0; j < 2; j++)
        #pragma unroll
        for (int py = 0; py < 2; py++) {
            unsigned lo, hi;
            UNPACK2(lo, hi, acc[j][py]);
            int oy = oy0 + 2 * my + py, ox = ox0 + mx;
            int oc = ocb + ocg * 4 + j * 2;
            atomicAdd(&out[(oc * HOUT + oy) * HOUT + ox],       __uint_as_float(lo));
            atomicAdd(&out[((oc + 1) * HOUT + oy) * HOUT + ox], __uint_as_float(hi));
        }

    // ---- fused head on the last-finishing conv4 block ----
    if (HEAD) {
        __shared__ unsigned s_last;
        __shared__ float l0[64], l1[64];
        __threadfence();
        __syncthreads();
        if (tid == 0) {
            unsigned total = gridDim.x * gridDim.y * gridDim.z;
            s_last = (atomicAdd(&g_done, 1u) == total - 1) ? 1u : 0u;
        }
        __syncthreads();
        if (s_last) {
            if (tid < 64) {
                __threadfence();
                int c = tid;
                const float* a4 = g_accs + Offs<4>::v;
                float sc = g_scale[256 + c], sh = g_shift[256 + c];
                float s = 0.0f;
                #pragma unroll 8
                for (int p = 0; p < 64; p++) s += fmaxf(fmaf(a4[c * 64 + p], sc, sh), 0.0f);
                float feat = s * (1.0f / 64.0f);
                l0[c] = feat * head_w[c];
                l1[c] = feat * head_w[64 + c];
            }
            __syncthreads();
            if (tid == 0) {
                float A = head_b[0], B = head_b[1];
                for (int i = 0; i < 64; i++) { A += l0[i]; B += l1[i]; }
                outp[0] = (B > A) ? 1 : 0;
            }
        }
    }
}

// ---------------- launch (6 graph nodes) ----------------
extern "C" void kernel_launch(void* const* d_in, const int* in_sizes, int n_in,
                              void* d_out, int out_size)
{
    const float* image   = (const float*)d_in[0];
    const float* conv0_w = (const float*)d_in[1];
    const float* conv0_b = (const float*)d_in[2];
    const float* convs_w = (const float*)d_in[3];
    const float* convs_b = (const float*)d_in[4];
    const float* bn_g    = (const float*)d_in[5];
    const float* bn_b    = (const float*)d_in[6];
    const float* bn_m    = (const float*)d_in[7];
    const float* bn_v    = (const float*)d_in[8];
    const float* head_w  = (const float*)d_in[9];
    const float* head_b  = (const float*)d_in[10];
    int* outp = (int*)d_out;

    scan_kernel<<<544, 256>>>(image, conv0_b, convs_b, bn_g, bn_b, bn_m, bn_v);
    front_kernel<<<256, 256>>>(image, conv0_w);
    conv88_kernel<1, 8><<<dim3(64, 8), 256>>>(convs_w);                                  // 512
    convoc_kernel<2, 8, false><<<dim3(16,  8, 2), 256>>>(convs_w, head_w, head_b, outp); // 256
    convoc_kernel<3, 4, false><<<dim3( 4, 16, 2), 256>>>(convs_w, head_w, head_b, outp); // 128
    convoc_kernel<4, 2, true ><<<dim3( 1, 32, 2), 256>>>(convs_w, head_w, head_b, outp); //  64
}

// round 16
// speedup vs baseline: 1.1188x; 1.0767x over previous
#include <cuda_runtime.h>
#include <math.h>

#define IMG_W 8192
typedef unsigned long long ull;

// ---------------- scratch ----------------
// acc0 64x128x128 @0, acc1 64x64x64 @1048576, acc2 64x32x32 @1310720,
// acc3 64x16x16 @1376256, acc4 64x8x8 @1392640
__device__ float g_accs[1396736];
__device__ int   g_bounds[4] = {1 << 30, -1, 1 << 30, -1};  // idempotent atomics -> replay-safe
__device__ float g_scale[320];
__device__ float g_shift[320];
__device__ unsigned g_done;

#define PACK2(dst, v)  asm("mov.b64 %0, {%1, %1};" : "=l"(dst) : "r"(__float_as_uint(v)))
#define FMA2(acc, a, b) asm("fma.rn.f32x2 %0, %1, %2, %0;" : "+l"(acc) : "l"(a), "l"(b))
#define UNPACK2(lo, hi, v) asm("mov.b64 {%0, %1}, %2;" : "=r"(lo), "=r"(hi) : "l"(v))

template<int L> struct Offs;
template<> struct Offs<0> { static const int v = 0; };
template<> struct Offs<1> { static const int v = 1048576; };
template<> struct Offs<2> { static const int v = 1310720; };
template<> struct Offs<3> { static const int v = 1376256; };
template<> struct Offs<4> { static const int v = 1392640; };

// PDL helpers (sm_90+): dependent prologue overlap
__device__ __forceinline__ void pdl_sync()    { cudaGridDependencySynchronize(); }
__device__ __forceinline__ void pdl_trigger() { cudaTriggerProgrammaticLaunchCompletion(); }

// ---------------- scan (merged with prep), 544 blocks -----------------------------
__global__ void scan_kernel(const float* __restrict__ img,
                            const float* __restrict__ conv0_b,
                            const float* __restrict__ convs_b,
                            const float* __restrict__ gamma,
                            const float* __restrict__ beta,
                            const float* __restrict__ mean,
                            const float* __restrict__ var)
{
    __shared__ int smn[256], smx[256];
    const int b = blockIdx.x, tid = threadIdx.x;
    const int gid = b * 256 + tid;

    for (int k = gid; k < 348160; k += 544 * 256) g_accs[1048576 + k] = 0.0f;
    if (gid < 320) {
        int l = gid >> 6, c = gid & 63;
        float sc = gamma[gid] / sqrtf(var[gid] + 1e-5f);
        float bb = (l == 0) ? conv0_b[c] : convs_b[(l - 1) * 64 + c];
        g_scale[gid] = sc;
        g_shift[gid] = (bb - mean[gid]) * sc + beta[gid];
    }
    if (gid == 0) g_done = 0u;

    int mn = 1 << 30, mx = -1;
    int lo_idx, hi_idx;
    if (b < 32) {                     // column scan, early exit
        lo_idx = 2; hi_idx = 3;
        int c = b * 256 + tid;
        float ref = img[c];
        bool found = false;
        for (int r = 1; r < IMG_W; r++) {
            found |= (img[(size_t)r * IMG_W + c] != ref);
            if (__all_sync(0xffffffffu, found)) break;
        }
        if (found) { mn = c; mx = c; }
    } else {                          // row scan: 2 rows per warp, parallel probes
        lo_idx = 0; hi_idx = 1;
        const int wid = tid >> 5, lane = tid & 31;
        const int row0 = ((b - 32) * 8 + wid) * 2;
        const float* rp0 = img + (size_t)row0 * IMG_W;
        const float* rp1 = rp0 + IMG_W;
        float v0 = rp0[lane];
        float v1 = rp1[lane];
        float ref0 = __shfl_sync(0xffffffffu, v0, 0);
        float ref1 = __shfl_sync(0xffffffffu, v1, 0);
        int f0 = __any_sync(0xffffffffu, v0 != ref0) ? 1 : 0;
        int f1 = __any_sync(0xffffffffu, v1 != ref1) ? 1 : 0;
        for (int base = 32; base < IMG_W && !f0; base += 32)
            f0 = __any_sync(0xffffffffu, rp0[base + lane] != ref0) ? 1 : 0;
        for (int base = 32; base < IMG_W && !f1; base += 32)
            f1 = __any_sync(0xffffffffu, rp1[base + lane] != ref1) ? 1 : 0;
        if (lane == 0) {
            if (f0) { mn = row0; mx = row0; }
            if (f1) { if (row0 + 1 < mn) mn = row0 + 1; if (row0 + 1 > mx) mx = row0 + 1; }
        }
    }

    smn[tid] = mn; smx[tid] = mx;
    __syncthreads();
    for (int s = 128; s > 0; s >>= 1) {
        if (tid < s) { smn[tid] = min(smn[tid], smn[tid + s]); smx[tid] = max(smx[tid], smx[tid + s]); }
        __syncthreads();
    }
    if (tid == 0 && smx[0] >= 0) {
        atomicMin(&g_bounds[lo_idx], smn[0]);
        atomicMax(&g_bounds[hi_idx], smx[0]);
    }
    pdl_trigger();
}

// ---------------- fused crop/resize + dilate + conv0 (8x8 tiles, 256 blocks) -----
__global__ void front_kernel(const float* __restrict__ img, const float* __restrict__ w0)
{
    __shared__ float s_res[21 * 21];
    __shared__ float s_dil[17 * 17];
    __shared__ float s_w[576];
    const int b = blockIdx.x, tid = threadIdx.x;
    const int ty = b >> 4, tx = b & 15;
    const int oy0 = ty * 8, ox0 = tx * 8;

    // independent prologue: stage conv0 weights before waiting on scan
    for (int i = tid; i < 576; i += 256) s_w[i] = w0[i];

    pdl_sync();   // scan's bounds/scale/zeroing now visible

    int top = g_bounds[0], bottom = g_bounds[1], left = g_bounds[2], right = g_bounds[3];
    if (bottom < 0) { top = 0; bottom = IMG_W - 1; }
    if (right  < 0) { left = 0; right  = IMG_W - 1; }

    const int ry0 = 2 * oy0 - 3, rx0 = 2 * ox0 - 3;
    const float szy = (float)(bottom - top + 1);
    const float szx = (float)(right - left + 1);
    for (int i = tid; i < 21 * 21; i += 256) {
        int r = i / 21, c = i - r * 21;
        int gy = ry0 + r, gx = rx0 + c;
        float val = 0.0f;
        if ((unsigned)gy < 256u && (unsigned)gx < 256u) {
            float cy = (float)top  + ((float)gy + 0.5f) * szy * (1.0f / 256.0f) - 0.5f;
            float cx = (float)left + ((float)gx + 0.5f) * szx * (1.0f / 256.0f) - 0.5f;
            float fy0 = floorf(cy), fx0 = floorf(cx);
            float wy = cy - fy0, wx = cx - fx0;
            int y0 = (int)fminf(fmaxf(fy0,        (float)top),  (float)bottom);
            int y1 = (int)fminf(fmaxf(fy0 + 1.0f, (float)top),  (float)bottom);
            int x0 = (int)fminf(fmaxf(fx0,        (float)left), (float)right);
            int x1 = (int)fminf(fmaxf(fx0 + 1.0f, (float)left), (float)right);
            float v00 = img[(size_t)y0 * IMG_W + x0];
            float v01 = img[(size_t)y0 * IMG_W + x1];
            float v10 = img[(size_t)y1 * IMG_W + x0];
            float v11 = img[(size_t)y1 * IMG_W + x1];
            float tr = v00 * (1.0f - wx) + v01 * wx;
            float br = v10 * (1.0f - wx) + v11 * wx;
            val = 255.0f - (tr * (1.0f - wy) + br * wy);
        }
        s_res[i] = val;
    }
    __syncthreads();

    for (int i = tid; i < 17 * 17; i += 256) {
        int r = i / 17, c = i - r * 17;
        int gy = 2 * oy0 - 1 + r, gx = 2 * ox0 - 1 + c;
        float val = 0.0f;
        if ((unsigned)gy < 256u && (unsigned)gx < 256u) {
            float s = 0.0f;
            #pragma unroll
            for (int dy = 0; dy <= 4; dy += 2)
                #pragma unroll
                for (int dx = 0; dx <= 4; dx += 2)
                    s += s_res[(r + dy) * 21 + (c + dx)];
            val = 255.0f - fminf(fmaxf(s, 0.0f), 255.0f);
        }
        s_dil[i] = val;
    }
    __syncthreads();

    const int px = tid >> 2, ocq = tid & 3;
    const int ly = px >> 3, lx = px & 7;
    float v[9];
    #pragma unroll
    for (int ky = 0; ky < 3; ky++)
        #pragma unroll
        for (int kx = 0; kx < 3; kx++)
            v[ky * 3 + kx] = s_dil[(2 * ly + ky) * 17 + (2 * lx + kx)];

    const int oy = oy0 + ly, ox = ox0 + lx;
    #pragma unroll 4
    for (int j = 0; j < 16; j++) {
        int oc = ocq * 16 + j;
        float a = 0.0f;
        #pragma unroll
        for (int k = 0; k < 9; k++) a = fmaf(v[k], s_w[oc * 9 + k], a);
        g_accs[(oc * 128 + oy) * 128 + ox] = a;
    }
    pdl_trigger();
}

// ---------------- conv1: 8x8-tile, all-64-oc kernel -------------------------------
template<int LAYER, int ICS>
__global__ void __launch_bounds__(256, 3) conv88_kernel(const float* __restrict__ convs_w)
{
    constexpr int HIN  = 256 >> LAYER;
    constexpr int HOUT = HIN >> 1;
    constexpr int TILESX = HOUT >> 3;
    const int tile = blockIdx.x;
    const int ty = tile / TILESX, tx = tile - ty * TILESX;
    const int oy0 = ty * 8, ox0 = tx * 8;
    const int ic0 = blockIdx.y * ICS;

    const float* __restrict__ in  = g_accs + Offs<LAYER - 1>::v;
    float* __restrict__ out       = g_accs + Offs<LAYER>::v;
    const float* __restrict__ w   = convs_w + (LAYER - 1) * 36864;
    const float* __restrict__ scl = g_scale + (LAYER - 1) * 64;
    const float* __restrict__ shf = g_shift + (LAYER - 1) * 64;

    __shared__ __align__(16) float s_w[ICS * 576];
    __shared__ __align__(16) float s_in[ICS * 340];

    const int tid = threadIdx.x;

    // independent prologue: weight LDGs (convs_w is a kernel input, no dependency)
    constexpr int WPO2 = ICS * 9 / 2;
    constexpr int W2 = 64 * WPO2;
    constexpr int W2IT = (W2 + 255) / 256;
    float2 wq[W2IT];
    #pragma unroll
    for (int i = 0; i < W2IT; i++) {
        int idx = tid + i * 256;
        if (idx < W2) {
            int oc = idx / WPO2, rem2 = idx - oc * WPO2;
            wq[i] = *reinterpret_cast<const float2*>(&w[oc * 576 + ic0 * 9 + rem2 * 2]);
        }
    }
    #pragma unroll
    for (int i = 0; i < W2IT; i++) {
        int idx = tid + i * 256;
        if (idx < W2) {
            int oc = idx / WPO2, rem2 = idx - oc * WPO2;
            int f0 = rem2 * 2;
            int ic_a = f0 / 9, k_a = f0 - ic_a * 9;
            s_w[(ic_a * 9 + k_a) * 64 + oc] = wq[i].x;
            int f1 = f0 + 1;
            int ic_b = f1 / 9, k_b = f1 - ic_b * 9;
            s_w[(ic_b * 9 + k_b) * 64 + oc] = wq[i].y;
        }
    }

    pdl_sync();   // predecessor output (acc0) + g_scale now visible

    constexpr int ITOT = ICS * 289;
    constexpr int IIT = (ITOT + 255) / 256;
    float it[IIT];
    const int iy0 = oy0 * 2 - 1, ix0 = ox0 * 2 - 1;
    #pragma unroll
    for (int i = 0; i < IIT; i++) {
        int idx = tid + i * 256;
        if (idx < ITOT) {
            int ch = idx / 289, pos = idx - ch * 289;
            int r = pos / 17, c = pos - r * 17;
            int gy = iy0 + r, gx = ix0 + c;
            bool inb = ((unsigned)gy < (unsigned)HIN) && ((unsigned)gx < (unsigned)HIN);
            it[i] = inb ? __ldg(&in[(ic0 + ch) * HIN * HIN + gy * HIN + gx]) : 0.0f;
        }
    }
    #pragma unroll
    for (int i = 0; i < IIT; i++) {
        int idx = tid + i * 256;
        if (idx < ITOT) {
            int ch = idx / 289, pos = idx - ch * 289;
            int r = pos / 17, c = pos - r * 17;
            int ic = ic0 + ch;
            s_in[ch * 340 + r * 20 + c] =
                fmaxf(fmaf(it[i], __ldg(&scl[ic]), __ldg(&shf[ic])), 0.0f);
        }
    }
    __syncthreads();

    const int ocg = tid & 15;
    const int sps = tid >> 4;
    const int my = sps >> 2, mx = sps & 3;

    ull acc[2][4];
    #pragma unroll
    for (int j = 0; j < 2; j++)
        #pragma unroll
        for (int p = 0; p < 4; p++) acc[j][p] = 0ull;

    const float* bp = s_in + (4 * my) * 20 + 4 * mx;

    float4 q[5]; float e[5];
    #pragma unroll
    for (int r = 0; r < 5; r++) {
        q[r] = *reinterpret_cast<const float4*>(bp + r * 20);
        e[r] = bp[r * 20 + 4];
    }

    #pragma unroll
    for (int icc = 0; icc < ICS; icc++) {
        float4 qn[5]; float en[5];
        if (icc + 1 < ICS) {
            const float* bpn = bp + (icc + 1) * 340;
            #pragma unroll
            for (int r = 0; r < 5; r++) {
                qn[r] = *reinterpret_cast<const float4*>(bpn + r * 20);
                en[r] = bpn[r * 20 + 4];
            }
        }
        float win[5][5];
        #pragma unroll
        for (int r = 0; r < 5; r++) {
            win[r][0] = q[r].x; win[r][1] = q[r].y;
            win[r][2] = q[r].z; win[r][3] = q[r].w; win[r][4] = e[r];
        }
        #pragma unroll
        for (int ky = 0; ky < 3; ky++)
            #pragma unroll
            for (int kx = 0; kx < 3; kx++) {
                const int k = ky * 3 + kx;
                ulonglong2 wv = reinterpret_cast<const ulonglong2*>(s_w)[(icc * 9 + k) * 16 + ocg];
                #pragma unroll
                for (int py = 0; py < 2; py++)
                    #pragma unroll
                    for (int px = 0; px < 2; px++) {
                        ull v2;
                        PACK2(v2, win[2 * py + ky][2 * px + kx]);
                        const int p = py * 2 + px;
                        FMA2(acc[0][p], v2, wv.x);
                        FMA2(acc[1][p], v2, wv.y);
                    }
            }
        if (icc + 1 < ICS) {
            #pragma unroll
            for (int r = 0; r < 5; r++) { q[r] = qn[r]; e[r] = en[r]; }
        }
    }

    #pragma unroll
    for (int j = 0; j < 2; j++)
        #pragma unroll
        for (int py = 0; py < 2; py++)
            #pragma unroll
            for (int px = 0; px < 2; px++) {
                unsigned lo, hi;
                UNPACK2(lo, hi, acc[j][py * 2 + px]);
                int oy = oy0 + 2 * my + py, ox = ox0 + 2 * mx + px;
                int oc = ocg * 4 + j * 2;
                atomicAdd(&out[(oc * HOUT + oy) * HOUT + ox], __uint_as_float(lo));
                atomicAdd(&out[((oc + 1) * HOUT + oy) * HOUT + ox], __uint_as_float(hi));
            }
    pdl_trigger();
}

// ---------------- conv2-4: convoc with DUPLICATED-INPUT smem ---------------------
template<int LAYER, int ICS, bool HEAD>
__global__ void __launch_bounds__(256, 2) convoc_kernel(
    const float* __restrict__ convs_w,
    const float* __restrict__ head_w,
    const float* __restrict__ head_b,
    int* __restrict__ outp)
{
    constexpr int HIN  = 256 >> LAYER;
    constexpr int HOUT = HIN >> 1;
    constexpr int TILESX = HOUT >> 3;
    constexpr int RSTR = 36;
    constexpr int CSTR = 17 * RSTR;
    const int tile = blockIdx.x;
    const int ty = tile / TILESX, tx = tile - ty * TILESX;
    const int oy0 = ty * 8, ox0 = tx * 8;
    const int ic0 = blockIdx.y * ICS;
    const int ocb = blockIdx.z * 32;

    const float* __restrict__ in  = g_accs + Offs<LAYER - 1>::v;
    float* __restrict__ out       = g_accs + Offs<LAYER>::v;
    const float* __restrict__ w   = convs_w + (LAYER - 1) * 36864;
    const float* __restrict__ scl = g_scale + (LAYER - 1) * 64;
    const float* __restrict__ shf = g_shift + (LAYER - 1) * 64;

    __shared__ __align__(16) float s_w[ICS * 288];
    __shared__ __align__(16) float s_in[ICS * CSTR];

    const int tid = threadIdx.x;

    // independent prologue: weight staging (reads only convs_w)
    constexpr int WPO2 = ICS * 9 / 2;
    constexpr int W2 = 32 * WPO2;
    constexpr int W2IT = (W2 + 255) / 256;
    float2 wq[W2IT];
    #pragma unroll
    for (int i = 0; i < W2IT; i++) {
        int idx = tid + i * 256;
        if (idx < W2) {
            int ocl = idx / WPO2, rem2 = idx - ocl * WPO2;
            wq[i] = *reinterpret_cast<const float2*>(&w[(ocb + ocl) * 576 + ic0 * 9 + rem2 * 2]);
        }
    }
    #pragma unroll
    for (int i = 0; i < W2IT; i++) {
        int idx = tid + i * 256;
        if (idx < W2) {
            int ocl = idx / WPO2, rem2 = idx - ocl * WPO2;
            int f0 = rem2 * 2;
            int ic_a = f0 / 9, k_a = f0 - ic_a * 9;
            s_w[(ic_a * 9 + k_a) * 32 + ocl] = wq[i].x;
            int f1 = f0 + 1;
            int ic_b = f1 / 9, k_b = f1 - ic_b * 9;
            s_w[(ic_b * 9 + k_b) * 32 + ocl] = wq[i].y;
        }
    }

    pdl_sync();   // predecessor conv output + g_scale + zeroed out-acc visible

    constexpr int ITOT = ICS * 289;
    constexpr int IIT = (ITOT + 255) / 256;
    float it[IIT];
    const int iy0 = oy0 * 2 - 1, ix0 = ox0 * 2 - 1;
    #pragma unroll
    for (int i = 0; i < IIT; i++) {
        int idx = tid + i * 256;
        if (idx < ITOT) {
            int ch = idx / 289, pos = idx - ch * 289;
            int r = pos / 17, c = pos - r * 17;
            int gy = iy0 + r, gx = ix0 + c;
            bool inb = ((unsigned)gy < (unsigned)HIN) && ((unsigned)gx < (unsigned)HIN);
            it[i] = inb ? __ldg(&in[(ic0 + ch) * HIN * HIN + gy * HIN + gx]) : 0.0f;
        }
    }
    #pragma unroll
    for (int i = 0; i < IIT; i++) {
        int idx = tid + i * 256;
        if (idx < ITOT) {
            int ch = idx / 289, pos = idx - ch * 289;
            int r = pos / 17, c = pos - r * 17;
            int ic = ic0 + ch;
            float vv = fmaxf(fmaf(it[i], __ldg(&scl[ic]), __ldg(&shf[ic])), 0.0f);
            ull dv; PACK2(dv, vv);
            *reinterpret_cast<ull*>(&s_in[ch * CSTR + r * RSTR + c * 2]) = dv;
        }
    }
    __syncthreads();

    const int ocg = tid & 7;
    const int sps = tid >> 3;
    const int my = sps >> 3, mx = sps & 7;

    ull acc[2][2];
    #pragma unroll
    for (int j = 0; j < 2; j++) { acc[j][0] = 0ull; acc[j][1] = 0ull; }

    const float* bp = s_in + (4 * my) * RSTR + (2 * mx) * 2;

    ulonglong2 a01[5]; ull a2[5];
    #pragma unroll
    for (int r = 0; r < 5; r++) {
        a01[r] = *reinterpret_cast<const ulonglong2*>(bp + r * RSTR);
        a2[r]  = *reinterpret_cast<const ull*>(bp + r * RSTR + 4);
    }

    #pragma unroll
    for (int icc = 0; icc < ICS; icc++) {
        ulonglong2 b01[5]; ull b2[5];
        if (icc + 1 < ICS) {
            const float* bpn = bp + (icc + 1) * CSTR;
            #pragma unroll
            for (int r = 0; r < 5; r++) {
                b01[r] = *reinterpret_cast<const ulonglong2*>(bpn + r * RSTR);
                b2[r]  = *reinterpret_cast<const ull*>(bpn + r * RSTR + 4);
            }
        }
        ull win[5][3];
        #pragma unroll
        for (int r = 0; r < 5; r++) {
            win[r][0] = a01[r].x; win[r][1] = a01[r].y; win[r][2] = a2[r];
        }
        #pragma unroll
        for (int ky = 0; ky < 3; ky++)
            #pragma unroll
            for (int kx = 0; kx < 3; kx++) {
                const int k = ky * 3 + kx;
                ulonglong2 wv = *reinterpret_cast<const ulonglong2*>(
                    s_w + (icc * 9 + k) * 32 + ocg * 4);
                #pragma unroll
                for (int py = 0; py < 2; py++) {
                    ull v2 = win[ky + 2 * py][kx];
                    FMA2(acc[0][py], v2, wv.x);
                    FMA2(acc[1][py], v2, wv.y);
                }
            }
        if (icc + 1 < ICS) {
            #pragma unroll
            for (int r = 0; r < 5; r++) { a01[r] = b01[r]; a2[r] = b2[r]; }
        }
    }

    #pragma unroll
    for (int j = 0; j < 2; j++)
        #pragma unroll
        for (int py = 0; py < 2; py++) {
            unsigned lo, hi;
            UNPACK2(lo, hi, acc[j][py]);
            int oy = oy0 + 2 * my + py, ox = ox0 + mx;
            int oc = ocb + ocg * 4 + j * 2;
            atomicAdd(&out[(oc * HOUT + oy) * HOUT + ox],       __uint_as_float(lo));
            atomicAdd(&out[((oc + 1) * HOUT + oy) * HOUT + ox], __uint_as_float(hi));
        }
    if (!HEAD) pdl_trigger();

    // ---- fused head on the last-finishing conv4 block ----
    if (HEAD) {
        __shared__ unsigned s_last;
        __shared__ float l0[64], l1[64];
        __threadfence();
        __syncthreads();
        if (tid == 0) {
            unsigned total = gridDim.x * gridDim.y * gridDim.z;
            s_last = (atomicAdd(&g_done, 1u) == total - 1) ? 1u : 0u;
        }
        __syncthreads();
        if (s_last) {
            if (tid < 64) {
                __threadfence();
                int c = tid;
                const float* a4 = g_accs + Offs<4>::v;
                float sc = g_scale[256 + c], sh = g_shift[256 + c];
                float s = 0.0f;
                #pragma unroll 8
                for (int p = 0; p < 64; p++) s += fmaxf(fmaf(a4[c * 64 + p], sc, sh), 0.0f);
                float feat = s * (1.0f / 64.0f);
                l0[c] = feat * head_w[c];
                l1[c] = feat * head_w[64 + c];
            }
            __syncthreads();
            if (tid == 0) {
                float A = head_b[0], B = head_b[1];
                for (int i = 0; i < 64; i++) { A += l0[i]; B += l1[i]; }
                outp[0] = (B > A) ? 1 : 0;
            }
        }
    }
}

// ---------------- launch (6 graph nodes, PDL-chained) ----------------
static inline void set_pdl(cudaLaunchConfig_t& cfg, cudaLaunchAttribute* attr)
{
    attr[0].id = cudaLaunchAttributeProgrammaticStreamSerialization;
    attr[0].val.programmaticStreamSerializationAllowed = 1;
    cfg.attrs = attr;
    cfg.numAttrs = 1;
}

extern "C" void kernel_launch(void* const* d_in, const int* in_sizes, int n_in,
                              void* d_out, int out_size)
{
    const float* image   = (const float*)d_in[0];
    const float* conv0_w = (const float*)d_in[1];
    const float* conv0_b = (const float*)d_in[2];
    const float* convs_w = (const float*)d_in[3];
    const float* convs_b = (const float*)d_in[4];
    const float* bn_g    = (const float*)d_in[5];
    const float* bn_b    = (const float*)d_in[6];
    const float* bn_m    = (const float*)d_in[7];
    const float* bn_v    = (const float*)d_in[8];
    const float* head_w  = (const float*)d_in[9];
    const float* head_b  = (const float*)d_in[10];
    int* outp = (int*)d_out;

    // node 0: scan (no predecessor -> plain launch)
    scan_kernel<<<544, 256>>>(image, conv0_b, convs_b, bn_g, bn_b, bn_m, bn_v);

    cudaLaunchAttribute attr[1];
    cudaLaunchConfig_t cfg = {};
    cfg.blockDim = dim3(256, 1, 1);
    set_pdl(cfg, attr);

    cfg.gridDim = dim3(256, 1, 1);
    cudaLaunchKernelEx(&cfg, front_kernel, image, conv0_w);

    cfg.gridDim = dim3(64, 8, 1);
    cudaLaunchKernelEx(&cfg, conv88_kernel<1, 8>, convs_w);

    cfg.gridDim = dim3(16, 8, 2);
    cudaLaunchKernelEx(&cfg, convoc_kernel<2, 8, false>, convs_w, head_w, head_b, outp);

    cfg.gridDim = dim3(4, 16, 2);
    cudaLaunchKernelEx(&cfg, convoc_kernel<3, 4, false>, convs_w, head_w, head_b, outp);

    cfg.gridDim = dim3(1, 32, 2);
    cudaLaunchKernelEx(&cfg, convoc_kernel<4, 2, true>, convs_w, head_w, head_b, outp);
}